// round 11
// baseline (speedup 1.0000x reference)
#include <cuda_runtime.h>
#include <cuda_fp16.h>

#define N_NODES 100000
#define NEDGES  1250000
#define D       64
#define H       8
// DH = 8, scale = 1/sqrt(8)

// Scratch (static __device__ arrays: allocation-free per harness rules)
__device__ float g_Q[N_NODES * D];
__device__ float g_K[N_NODES * D];
__device__ float g_V[N_NODES * D];
__device__ float g_Z[N_NODES * H];

// ---------------------------------------------------------------------------
// helpers
// ---------------------------------------------------------------------------
__device__ __forceinline__ void red_add_v4(float* p, float x, float y, float z, float w) {
    asm volatile("red.global.add.v4.f32 [%0], {%1, %2, %3, %4};"
                 :: "l"(p), "f"(x), "f"(y), "f"(z), "f"(w) : "memory");
}

// split a float2 into hi/lo packed f16x2 (hi + lo recovers ~22 mantissa bits)
__device__ __forceinline__ void split_f16x2(float2 v, unsigned& h, unsigned& l) {
    __half2 hb = __floats2half2_rn(v.x, v.y);
    float2 hf = __half22float2(hb);
    __half2 lb = __floats2half2_rn(v.x - hf.x, v.y - hf.y);
    h = *reinterpret_cast<unsigned*>(&hb);
    l = *reinterpret_cast<unsigned*>(&lb);
}

__device__ __forceinline__ unsigned pack_f16x2(float a, float b) {
    __half2 hb = __floats2half2_rn(a, b);
    return *reinterpret_cast<unsigned*>(&hb);
}

// D += A(f16) * B(f16), m16n8k16, f32 accumulate
__device__ __forceinline__ void mma_f16(float* c, const unsigned* a,
                                        unsigned b0, unsigned b1) {
    asm volatile(
        "mma.sync.aligned.m16n8k16.row.col.f32.f16.f16.f32 "
        "{%0,%1,%2,%3}, {%4,%5,%6,%7}, {%8,%9}, {%0,%1,%2,%3};"
        : "+f"(c[0]), "+f"(c[1]), "+f"(c[2]), "+f"(c[3])
        : "r"(a[0]), "r"(a[1]), "r"(a[2]), "r"(a[3]), "r"(b0), "r"(b1));
}

__device__ __forceinline__ void bar_sync(int id)   {
    asm volatile("bar.sync %0, 64;" :: "r"(id) : "memory");
}
__device__ __forceinline__ void bar_arrive(int id) {
    asm volatile("bar.arrive %0, 64;" :: "r"(id) : "memory");
}

// ---------------------------------------------------------------------------
// K1: QKV projections via fp16-split tensor-core mma, 3-pass (hh + hl + lh;
// dropped ll ~2^-24 — effectively fp32-exact). One warp per 16 nodes.
// Also zeroes out[] rows and g_Z rows. N_NODES % 16 == 0.
// ---------------------------------------------------------------------------
__global__ __launch_bounds__(256) void proj_kernel(
    const float* __restrict__ x,
    const float* __restrict__ WQ,
    const float* __restrict__ WK,
    const float* __restrict__ WV,
    float* __restrict__ out)
{
    // [mat][ntile][kstep][lane] = (bh0, bh1, bl0, bl1)
    __shared__ uint4 sB[3][8][4][32];   // 48 KB

    const int tid = threadIdx.x;
    const float* Ws[3] = {WQ, WK, WV};
    for (int t = tid; t < 3 * 1024; t += 256) {
        int w = t >> 10, rem = t & 1023;
        int n = rem >> 7, k = (rem >> 5) & 3, l = rem & 31;
        int tig = l & 3, grp = l >> 2;
        int col = n * 8 + grp;
        int r0 = k * 16 + 2 * tig;
        const float* W = Ws[w];
        float2 w0 = make_float2(__ldg(&W[r0 * D + col]),       __ldg(&W[(r0 + 1) * D + col]));
        float2 w1 = make_float2(__ldg(&W[(r0 + 8) * D + col]), __ldg(&W[(r0 + 9) * D + col]));
        unsigned h0, l0, h1, l1;
        split_f16x2(w0, h0, l0);
        split_f16x2(w1, h1, l1);
        sB[w][n][k][l] = make_uint4(h0, h1, l0, l1);
    }
    __syncthreads();

    const int warp = tid >> 5;
    const int lane = tid & 31;
    const int tile = blockIdx.x * 8 + warp;     // 16-node tile index
    if (tile >= N_NODES / 16) return;

    const int grp = lane >> 2;    // 0..7
    const int tig = lane & 3;     // 0..3
    const long row0 = (long)tile * 16 + grp;
    const long row1 = row0 + 8;

    // --- A fragments from x (hi/lo fp16 split) ---
    unsigned Ah[4][4], Al[4][4];
#pragma unroll
    for (int k = 0; k < 4; k++) {
        float2 x0 = __ldg(reinterpret_cast<const float2*>(x + row0 * D + k * 16 + 2 * tig));
        float2 x1 = __ldg(reinterpret_cast<const float2*>(x + row1 * D + k * 16 + 2 * tig));
        float2 x2 = __ldg(reinterpret_cast<const float2*>(x + row0 * D + k * 16 + 8 + 2 * tig));
        float2 x3 = __ldg(reinterpret_cast<const float2*>(x + row1 * D + k * 16 + 8 + 2 * tig));
        split_f16x2(x0, Ah[k][0], Al[k][0]);
        split_f16x2(x1, Ah[k][1], Al[k][1]);
        split_f16x2(x2, Ah[k][2], Al[k][2]);
        split_f16x2(x3, Ah[k][3], Al[k][3]);
    }

    float* Outs[3] = {g_Q, g_K, g_V};
#pragma unroll
    for (int w = 0; w < 3; w++) {
        float* O = Outs[w];
#pragma unroll
        for (int n = 0; n < 8; n++) {
            uint4 b[4];
#pragma unroll
            for (int k = 0; k < 4; k++) b[k] = sB[w][n][k][lane];

            float c1[4] = {0.f, 0.f, 0.f, 0.f};
            float c2[4] = {0.f, 0.f, 0.f, 0.f};
            float c3[4] = {0.f, 0.f, 0.f, 0.f};
#pragma unroll
            for (int k = 0; k < 4; k++) {
                mma_f16(c1, Ah[k], b[k].x, b[k].y);   // hh
                mma_f16(c2, Ah[k], b[k].z, b[k].w);   // h*l
                mma_f16(c3, Al[k], b[k].x, b[k].y);   // l*h
            }

            int cc = n * 8 + 2 * tig;
            *reinterpret_cast<float2*>(&O[row0 * D + cc]) =
                make_float2(c1[0] + c2[0] + c3[0], c1[1] + c2[1] + c3[1]);
            *reinterpret_cast<float2*>(&O[row1 * D + cc]) =
                make_float2(c1[2] + c2[2] + c3[2], c1[3] + c2[3] + c3[3]);
        }
    }

    // --- zero accumulators for these 16 nodes ---
    float4 z4 = make_float4(0.f, 0.f, 0.f, 0.f);
    float4* o4 = reinterpret_cast<float4*>(out) + (long)tile * 256;  // 16 rows * 16 f4
#pragma unroll
    for (int i = 0; i < 8; i++) o4[i * 32 + lane] = z4;
    reinterpret_cast<float4*>(g_Z)[(long)tile * 32 + lane] = z4;
}

// ---------------------------------------------------------------------------
// K2: WARP-SPECIALIZED fused edge kernel.
// Block = 8 warps = 4 (producer, consumer) pairs, double-buffered sEf tiles.
//  Producer warp: phase A — ea[16x64] @ WE via fp16 2-pass split mma
//                 (64 m16n8k16 per tile) -> sEf[pair][buf].
//  Consumer warp: phase B — 16 lanes/edge, prefetches sd + first gathers
//                 BEFORE waiting on `full` (wait hides gather latency),
//                 then score + red.add.v4 scatter + Z atomic.
// Named barriers per pair, ONE PER (direction, buf) — ids pair*4 + {0,1} =
// full[buf], pair*4 + {2,3} = empty[buf]. Per-buffer barriers are required:
// a single shared barrier per direction would let the producer's two arrives
// trip the barrier with no waiter and deadlock (round-10 bug). Barrier 0
// aliases __syncthreads but is strictly serialized: the one block-wide sync
// completes (state resets) before any pair-0 barrier traffic, and no later
// __syncthreads exists.
// Each warp holds only one phase's registers -> higher occupancy; producer
// mma issue overlaps consumer gather stalls on the same SMSP.
// NEDGES % 16 == 0 -> all tiles full.
// ---------------------------------------------------------------------------
__global__ __launch_bounds__(256) void fused_edge_ws_kernel(
    const float* __restrict__ ea,
    const float* __restrict__ WE,
    const int* __restrict__ ei,
    float* __restrict__ out)
{
    __shared__ uint2 sB[8][4][32];        // 8 KB  (WE fp16 B-fragments)
    __shared__ float sEf[4][2][16][64];   // 32 KB (pair, buf, row, col)

    const int tid = threadIdx.x;

    // --- stage WE as packed fp16 B-fragments ---
    for (int t = tid; t < 1024; t += 256) {
        int n = t >> 7, k = (t >> 5) & 3, l = t & 31;
        int tig = l & 3, grp = l >> 2;
        int col = n * 8 + grp;
        int r0 = k * 16 + 2 * tig;
        unsigned b0 = pack_f16x2(__ldg(&WE[r0 * D + col]),       __ldg(&WE[(r0 + 1) * D + col]));
        unsigned b1 = pack_f16x2(__ldg(&WE[(r0 + 8) * D + col]), __ldg(&WE[(r0 + 9) * D + col]));
        sB[n][k][l] = make_uint2(b0, b1);
    }
    __syncthreads();

    const int warp = tid >> 5;
    const int lane = tid & 31;
    const int pair = warp >> 1;
    const int NT = NEDGES / 16;            // 78125 tiles
    const int npairs = gridDim.x * 4;
    const int gp = blockIdx.x * 4 + pair;  // global pair id

    if ((warp & 1) == 0) {
        // ================= PRODUCER =================
        const int grp = lane >> 2;    // 0..7
        const int tig = lane & 3;     // 0..3
        const int swz = grp << 3;

        int buf = 0, j = 0;
        for (int t = gp; t < NT; t += npairs, j++, buf ^= 1) {
            if (j >= 2) bar_sync(pair * 4 + 2 + buf);   // wait buf empty

            const long row0 = (long)t * 16 + grp;
            const long row1 = row0 + 8;

            unsigned Ah[4][4], Al[4][4];
#pragma unroll
            for (int k = 0; k < 4; k++) {
                float2 x0 = __ldcs(reinterpret_cast<const float2*>(ea + row0 * D + k * 16 + 2 * tig));
                float2 x1 = __ldcs(reinterpret_cast<const float2*>(ea + row1 * D + k * 16 + 2 * tig));
                float2 x2 = __ldcs(reinterpret_cast<const float2*>(ea + row0 * D + k * 16 + 8 + 2 * tig));
                float2 x3 = __ldcs(reinterpret_cast<const float2*>(ea + row1 * D + k * 16 + 8 + 2 * tig));
                split_f16x2(x0, Ah[k][0], Al[k][0]);
                split_f16x2(x1, Ah[k][1], Al[k][1]);
                split_f16x2(x2, Ah[k][2], Al[k][2]);
                split_f16x2(x3, Ah[k][3], Al[k][3]);
            }

#pragma unroll
            for (int n = 0; n < 8; n++) {
                uint2 b[4];
#pragma unroll
                for (int k = 0; k < 4; k++) b[k] = sB[n][k][lane];

                float c1[4] = {0.f, 0.f, 0.f, 0.f};
                float c2[4] = {0.f, 0.f, 0.f, 0.f};
#pragma unroll
                for (int k = 0; k < 4; k++) {
                    mma_f16(c1, Ah[k], b[k].x, b[k].y);   // hi x W
                    mma_f16(c2, Al[k], b[k].x, b[k].y);   // lo x W
                }

                int colw = (8 * n + 2 * tig) ^ swz;
                *reinterpret_cast<float2*>(&sEf[pair][buf][grp][colw]) =
                    make_float2(c1[0] + c2[0], c1[1] + c2[1]);
                *reinterpret_cast<float2*>(&sEf[pair][buf][grp + 8][colw]) =
                    make_float2(c1[2] + c2[2], c1[3] + c2[3]);
            }

            __threadfence_block();          // STS visible before arrive
            bar_arrive(pair * 4 + buf);     // signal buf full
        }
    } else {
        // ================= CONSUMER =================
        const int half = lane >> 4;
        const int g    = lane & 15;

        int buf = 0;
        for (int t = gp; t < NT; t += npairs, buf ^= 1) {
            const int base = t * 16;

            // prefetch indices + first two edge gathers BEFORE the full-wait
            int sd = __ldg(&ei[(lane >> 4) * NEDGES + base + (lane & 15)]);
            int s0 = __shfl_sync(0xFFFFFFFFu, sd, half);
            int d0 = __shfl_sync(0xFFFFFFFFu, sd, 16 + half);
            int s1 = __shfl_sync(0xFFFFFFFFu, sd, 2 + half);
            int d1 = __shfl_sync(0xFFFFFFFFu, sd, 18 + half);
            float4 kk0 = __ldg(reinterpret_cast<const float4*>(&g_K[(long)s0 * D + 4 * g]));
            float4 qq0 = __ldg(reinterpret_cast<const float4*>(&g_Q[(long)d0 * D + 4 * g]));
            float4 vv0 = __ldg(reinterpret_cast<const float4*>(&g_V[(long)s0 * D + 4 * g]));
            float4 kk1 = __ldg(reinterpret_cast<const float4*>(&g_K[(long)s1 * D + 4 * g]));
            float4 qq1 = __ldg(reinterpret_cast<const float4*>(&g_Q[(long)d1 * D + 4 * g]));

            bar_sync(pair * 4 + buf);       // wait buf full

            int s2, d2;
            float4 kk2, qq2, vv1;
#pragma unroll
            for (int it = 0; it < 8; it++) {
                if (it < 7)
                    vv1 = __ldg(reinterpret_cast<const float4*>(&g_V[(long)s1 * D + 4 * g]));
                if (it < 6) {
                    s2 = __shfl_sync(0xFFFFFFFFu, sd, (it + 2) * 2 + half);
                    d2 = __shfl_sync(0xFFFFFFFFu, sd, 16 + (it + 2) * 2 + half);
                    kk2 = __ldg(reinterpret_cast<const float4*>(&g_K[(long)s2 * D + 4 * g]));
                    qq2 = __ldg(reinterpret_cast<const float4*>(&g_Q[(long)d2 * D + 4 * g]));
                }

                int r = it * 2 + half;
                float4 ef = *reinterpret_cast<const float4*>(
                    &sEf[pair][buf][r][(4 * g) ^ ((r & 7) << 3)]);

                float p = (kk0.x * qq0.x) * ef.x;
                p = fmaf(kk0.y * qq0.y, ef.y, p);
                p = fmaf(kk0.z * qq0.z, ef.z, p);
                p = fmaf(kk0.w * qq0.w, ef.w, p);
                p += __shfl_xor_sync(0xFFFFFFFFu, p, 1);

                // clamp in p-domain (+-5*sqrt(8)); exp(x/sqrt8)=2^(x*log2e/sqrt8)
                float sv = fminf(14.142135623730951f, fmaxf(-14.142135623730951f, p));
                float sc = exp2f(sv * 0.51002501915290554f);

                red_add_v4(&out[(long)d0 * D + 4 * g],
                           vv0.x * sc, vv0.y * sc, vv0.z * sc, vv0.w * sc);
                if ((g & 1) == 0)
                    atomicAdd(&g_Z[d0 * H + (g >> 1)], sc);

                kk0 = kk1; qq0 = qq1; vv0 = vv1; s0 = s1; d0 = d1;
                kk1 = kk2; qq1 = qq2; s1 = s2; d1 = d2;
            }

            bar_arrive(pair * 4 + 2 + buf); // signal buf empty
        }
    }
}

// ---------------------------------------------------------------------------
// K3: out = wV / (Z + 1e-6)   (one float4 per thread)
// ---------------------------------------------------------------------------
__global__ void div_kernel(float4* __restrict__ out4) {
    int i = blockIdx.x * blockDim.x + threadIdx.x;
    if (i >= (N_NODES * D) / 4) return;
    int n  = i >> 4;           // 16 float4 per node
    int c4 = i & 15;
    int h  = c4 >> 1;          // head = (4*c4)/8
    float r = 1.0f / (g_Z[n * H + h] + 1e-6f);
    float4 v = out4[i];
    v.x *= r; v.y *= r; v.z *= r; v.w *= r;
    out4[i] = v;
}

// ---------------------------------------------------------------------------
extern "C" void kernel_launch(void* const* d_in, const int* in_sizes, int n_in,
                              void* d_out, int out_size)
{
    const float* x   = (const float*)d_in[0];
    const float* ea  = (const float*)d_in[1];
    const float* WQ  = (const float*)d_in[2];
    const float* WK  = (const float*)d_in[3];
    const float* WV  = (const float*)d_in[4];
    const float* WE  = (const float*)d_in[5];
    const int*   ei  = (const int*)d_in[6];
    float* out = (float*)d_out;

    (void)in_sizes; (void)n_in; (void)out_size;

    proj_kernel<<<(N_NODES / 16 + 7) / 8, 256>>>(x, WQ, WK, WV, out);
    fused_edge_ws_kernel<<<1184, 256>>>(ea, WE, ei, out);
    div_kernel<<<(N_NODES * D / 4 + 255) / 256, 256>>>((float4*)out);
}

// round 12
// speedup vs baseline: 1.1016x; 1.1016x over previous
#include <cuda_runtime.h>
#include <cuda_fp16.h>

#define N_NODES 100000
#define NEDGES  1250000
#define D       64
#define H       8
#define NB      391          // ceil(N_NODES/256)
// DH = 8, scale = 1/sqrt(8)

// Scratch (static __device__ arrays: allocation-free per harness rules)
__device__ float g_Q[N_NODES * D];
__device__ float g_K[N_NODES * D];
__device__ float g_V[N_NODES * D];
__device__ float g_Z[N_NODES * H];
__device__ int   g_cnt[N_NODES];
__device__ int   g_off[N_NODES];
__device__ int   g_bsum[NB];
__device__ int   g_boff[NB];
__device__ int   g_perm[NEDGES];        // sorted-pos -> original edge id
__device__ int   g_sds[2 * NEDGES];     // [0]=src, [1]=dst in sorted order

// ---------------------------------------------------------------------------
// helpers
// ---------------------------------------------------------------------------
__device__ __forceinline__ void red_add_v4(float* p, float x, float y, float z, float w) {
    asm volatile("red.global.add.v4.f32 [%0], {%1, %2, %3, %4};"
                 :: "l"(p), "f"(x), "f"(y), "f"(z), "f"(w) : "memory");
}

// split a float2 into hi/lo packed f16x2 (hi + lo recovers ~22 mantissa bits)
__device__ __forceinline__ void split_f16x2(float2 v, unsigned& h, unsigned& l) {
    __half2 hb = __floats2half2_rn(v.x, v.y);
    float2 hf = __half22float2(hb);
    __half2 lb = __floats2half2_rn(v.x - hf.x, v.y - hf.y);
    h = *reinterpret_cast<unsigned*>(&hb);
    l = *reinterpret_cast<unsigned*>(&lb);
}

__device__ __forceinline__ unsigned pack_f16x2(float a, float b) {
    __half2 hb = __floats2half2_rn(a, b);
    return *reinterpret_cast<unsigned*>(&hb);
}

// D += A(f16) * B(f16), m16n8k16, f32 accumulate
__device__ __forceinline__ void mma_f16(float* c, const unsigned* a,
                                        unsigned b0, unsigned b1) {
    asm volatile(
        "mma.sync.aligned.m16n8k16.row.col.f32.f16.f16.f32 "
        "{%0,%1,%2,%3}, {%4,%5,%6,%7}, {%8,%9}, {%0,%1,%2,%3};"
        : "+f"(c[0]), "+f"(c[1]), "+f"(c[2]), "+f"(c[3])
        : "r"(a[0]), "r"(a[1]), "r"(a[2]), "r"(a[3]), "r"(b0), "r"(b1));
}

// ---------------------------------------------------------------------------
// Counting sort by dst: K_a zero counters; K_b histogram; K_c/K_d/K_e scan;
// K_f scatter (perm + reordered src/dst).
// ---------------------------------------------------------------------------
__global__ void zero_cnt_kernel() {
    int i = blockIdx.x * blockDim.x + threadIdx.x;
    if (i < N_NODES) g_cnt[i] = 0;
}

__global__ void hist_kernel(const int* __restrict__ ei) {
    int e = blockIdx.x * blockDim.x + threadIdx.x;
    if (e < NEDGES) atomicAdd(&g_cnt[__ldg(&ei[NEDGES + e])], 1);
}

__global__ void scan1_kernel() {
    __shared__ int s[256];
    int tid = threadIdx.x;
    int i = blockIdx.x * 256 + tid;
    s[tid] = (i < N_NODES) ? g_cnt[i] : 0;
    __syncthreads();
    for (int o = 128; o > 0; o >>= 1) {
        if (tid < o) s[tid] += s[tid + o];
        __syncthreads();
    }
    if (tid == 0) g_bsum[blockIdx.x] = s[0];
}

__global__ void scan2_kernel() {
    __shared__ int s[512];
    int tid = threadIdx.x;
    int v = (tid < NB) ? g_bsum[tid] : 0;
    s[tid] = v;
    __syncthreads();
    for (int o = 1; o < 512; o <<= 1) {
        int t = (tid >= o) ? s[tid - o] : 0;
        __syncthreads();
        s[tid] += t;
        __syncthreads();
    }
    if (tid < NB) g_boff[tid] = s[tid] - v;   // exclusive
}

__global__ void scan3_kernel() {
    __shared__ int s[256];
    int tid = threadIdx.x;
    int i = blockIdx.x * 256 + tid;
    int v = (i < N_NODES) ? g_cnt[i] : 0;
    s[tid] = v;
    __syncthreads();
    for (int o = 1; o < 256; o <<= 1) {
        int t = (tid >= o) ? s[tid - o] : 0;
        __syncthreads();
        s[tid] += t;
        __syncthreads();
    }
    if (i < N_NODES) g_off[i] = s[tid] - v + g_boff[blockIdx.x];
}

__global__ void scatter_kernel(const int* __restrict__ ei) {
    int e = blockIdx.x * blockDim.x + threadIdx.x;
    if (e >= NEDGES) return;
    int sN = __ldg(&ei[e]);
    int dN = __ldg(&ei[NEDGES + e]);
    int pos = atomicAdd(&g_off[dN], 1);
    g_perm[pos] = e;
    g_sds[pos] = sN;
    g_sds[NEDGES + pos] = dN;
}

// ---------------------------------------------------------------------------
// K1: QKV projections via fp16-split tensor-core mma, 3-pass (hh + hl + lh).
// One warp per 16 nodes. Also zeroes out[] rows and g_Z rows.
// ---------------------------------------------------------------------------
__global__ __launch_bounds__(256) void proj_kernel(
    const float* __restrict__ x,
    const float* __restrict__ WQ,
    const float* __restrict__ WK,
    const float* __restrict__ WV,
    float* __restrict__ out)
{
    __shared__ uint4 sB[3][8][4][32];   // 48 KB

    const int tid = threadIdx.x;
    const float* Ws[3] = {WQ, WK, WV};
    for (int t = tid; t < 3 * 1024; t += 256) {
        int w = t >> 10, rem = t & 1023;
        int n = rem >> 7, k = (rem >> 5) & 3, l = rem & 31;
        int tig = l & 3, grp = l >> 2;
        int col = n * 8 + grp;
        int r0 = k * 16 + 2 * tig;
        const float* W = Ws[w];
        float2 w0 = make_float2(__ldg(&W[r0 * D + col]),       __ldg(&W[(r0 + 1) * D + col]));
        float2 w1 = make_float2(__ldg(&W[(r0 + 8) * D + col]), __ldg(&W[(r0 + 9) * D + col]));
        unsigned h0, l0, h1, l1;
        split_f16x2(w0, h0, l0);
        split_f16x2(w1, h1, l1);
        sB[w][n][k][l] = make_uint4(h0, h1, l0, l1);
    }
    __syncthreads();

    const int warp = tid >> 5;
    const int lane = tid & 31;
    const int tile = blockIdx.x * 8 + warp;
    if (tile >= N_NODES / 16) return;

    const int grp = lane >> 2;
    const int tig = lane & 3;
    const long row0 = (long)tile * 16 + grp;
    const long row1 = row0 + 8;

    unsigned Ah[4][4], Al[4][4];
#pragma unroll
    for (int k = 0; k < 4; k++) {
        float2 x0 = __ldg(reinterpret_cast<const float2*>(x + row0 * D + k * 16 + 2 * tig));
        float2 x1 = __ldg(reinterpret_cast<const float2*>(x + row1 * D + k * 16 + 2 * tig));
        float2 x2 = __ldg(reinterpret_cast<const float2*>(x + row0 * D + k * 16 + 8 + 2 * tig));
        float2 x3 = __ldg(reinterpret_cast<const float2*>(x + row1 * D + k * 16 + 8 + 2 * tig));
        split_f16x2(x0, Ah[k][0], Al[k][0]);
        split_f16x2(x1, Ah[k][1], Al[k][1]);
        split_f16x2(x2, Ah[k][2], Al[k][2]);
        split_f16x2(x3, Ah[k][3], Al[k][3]);
    }

    float* Outs[3] = {g_Q, g_K, g_V};
#pragma unroll
    for (int w = 0; w < 3; w++) {
        float* O = Outs[w];
#pragma unroll
        for (int n = 0; n < 8; n++) {
            uint4 b[4];
#pragma unroll
            for (int k = 0; k < 4; k++) b[k] = sB[w][n][k][lane];

            float c1[4] = {0.f, 0.f, 0.f, 0.f};
            float c2[4] = {0.f, 0.f, 0.f, 0.f};
            float c3[4] = {0.f, 0.f, 0.f, 0.f};
#pragma unroll
            for (int k = 0; k < 4; k++) {
                mma_f16(c1, Ah[k], b[k].x, b[k].y);
                mma_f16(c2, Ah[k], b[k].z, b[k].w);
                mma_f16(c3, Al[k], b[k].x, b[k].y);
            }

            int cc = n * 8 + 2 * tig;
            *reinterpret_cast<float2*>(&O[row0 * D + cc]) =
                make_float2(c1[0] + c2[0] + c3[0], c1[1] + c2[1] + c3[1]);
            *reinterpret_cast<float2*>(&O[row1 * D + cc]) =
                make_float2(c1[2] + c2[2] + c3[2], c1[3] + c2[3] + c3[3]);
        }
    }

    float4 z4 = make_float4(0.f, 0.f, 0.f, 0.f);
    float4* o4 = reinterpret_cast<float4*>(out) + (long)tile * 256;
#pragma unroll
    for (int i = 0; i < 8; i++) o4[i * 32 + lane] = z4;
    reinterpret_cast<float4*>(g_Z)[(long)tile * 32 + lane] = z4;
}

// ---------------------------------------------------------------------------
// K2: FUSED edge kernel over DST-SORTED edges. Per warp = 16 sorted edges.
//  Phase A: Ef tile via fp16 2-pass split mma, rows gathered through g_perm.
//  Phase B: half-warp processes 8 CONSECUTIVE sorted edges; V*sc and sc are
//           accumulated in registers across same-dst runs and flushed with
//           one red.add.v4 per run (~5x fewer scatter requests); Q gathers
//           within a run hit L1.
// ---------------------------------------------------------------------------
__global__ __launch_bounds__(256) void fused_edge_kernel(
    const float* __restrict__ ea,
    const float* __restrict__ WE,
    float* __restrict__ out)
{
    __shared__ uint2 sB[8][4][32];     // 8 KB  (WE fp16 B-fragments)
    __shared__ float sEf[8][16][64];   // 32 KB (per-warp 16x64 Ef tiles)

    const int tid = threadIdx.x;

    for (int t = tid; t < 1024; t += 256) {
        int n = t >> 7, k = (t >> 5) & 3, l = t & 31;
        int tig = l & 3, grp = l >> 2;
        int col = n * 8 + grp;
        int r0 = k * 16 + 2 * tig;
        unsigned b0 = pack_f16x2(__ldg(&WE[r0 * D + col]),       __ldg(&WE[(r0 + 1) * D + col]));
        unsigned b1 = pack_f16x2(__ldg(&WE[(r0 + 8) * D + col]), __ldg(&WE[(r0 + 9) * D + col]));
        sB[n][k][l] = make_uint2(b0, b1);
    }
    __syncthreads();

    const int warp = tid >> 5;
    const int lane = tid & 31;
    const int base = (blockIdx.x * 8 + warp) * 16;
    if (base >= NEDGES) return;

    // sorted-order metadata: lanes 0-15 = src, lanes 16-31 = dst; perm for ea
    int sd = __ldg(&g_sds[(lane >> 4) * NEDGES + base + (lane & 15)]);
    int pe = __ldg(&g_perm[base + (lane & 15)]);

    const int half = lane >> 4;
    const int g    = lane & 15;

    // edge-0/1 gathers (contiguous split: half h owns edges h*8 .. h*8+7)
    int s0 = __shfl_sync(0xFFFFFFFFu, sd, half * 8);
    int d0 = __shfl_sync(0xFFFFFFFFu, sd, 16 + half * 8);
    int s1 = __shfl_sync(0xFFFFFFFFu, sd, half * 8 + 1);
    int d1 = __shfl_sync(0xFFFFFFFFu, sd, 16 + half * 8 + 1);
    float4 kk0 = __ldg(reinterpret_cast<const float4*>(&g_K[(long)s0 * D + 4 * g]));
    float4 qq0 = __ldg(reinterpret_cast<const float4*>(&g_Q[(long)d0 * D + 4 * g]));
    float4 vv0 = __ldg(reinterpret_cast<const float4*>(&g_V[(long)s0 * D + 4 * g]));
    float4 kk1 = __ldg(reinterpret_cast<const float4*>(&g_K[(long)s1 * D + 4 * g]));
    float4 qq1 = __ldg(reinterpret_cast<const float4*>(&g_Q[(long)d1 * D + 4 * g]));

    const int grp = lane >> 2;
    const int tig = lane & 3;
    const long rowA = __shfl_sync(0xFFFFFFFFu, pe, grp);       // ea row, frag row grp
    const long rowB = __shfl_sync(0xFFFFFFFFu, pe, grp + 8);   // ea row, frag row grp+8

    // --- A fragments (permuted rows; each row fully read as 32B sectors) ---
    unsigned Ah[4][4], Al[4][4];
#pragma unroll
    for (int k = 0; k < 4; k++) {
        float2 x0 = __ldcs(reinterpret_cast<const float2*>(ea + rowA * D + k * 16 + 2 * tig));
        float2 x1 = __ldcs(reinterpret_cast<const float2*>(ea + rowB * D + k * 16 + 2 * tig));
        float2 x2 = __ldcs(reinterpret_cast<const float2*>(ea + rowA * D + k * 16 + 8 + 2 * tig));
        float2 x3 = __ldcs(reinterpret_cast<const float2*>(ea + rowB * D + k * 16 + 8 + 2 * tig));
        split_f16x2(x0, Ah[k][0], Al[k][0]);
        split_f16x2(x1, Ah[k][1], Al[k][1]);
        split_f16x2(x2, Ah[k][2], Al[k][2]);
        split_f16x2(x3, Ah[k][3], Al[k][3]);
    }

    const int swz = grp << 3;
#pragma unroll
    for (int n = 0; n < 8; n++) {
        uint2 b[4];
#pragma unroll
        for (int k = 0; k < 4; k++) b[k] = sB[n][k][lane];

        float c1[4] = {0.f, 0.f, 0.f, 0.f};
        float c2[4] = {0.f, 0.f, 0.f, 0.f};
#pragma unroll
        for (int k = 0; k < 4; k++) {
            mma_f16(c1, Ah[k], b[k].x, b[k].y);
            mma_f16(c2, Al[k], b[k].x, b[k].y);
        }

        int colw = (8 * n + 2 * tig) ^ swz;
        *reinterpret_cast<float2*>(&sEf[warp][grp][colw]) =
            make_float2(c1[0] + c2[0], c1[1] + c2[1]);
        *reinterpret_cast<float2*>(&sEf[warp][grp + 8][colw]) =
            make_float2(c1[2] + c2[2], c1[3] + c2[3]);
    }
    __syncwarp();

    // --- phase B: segmented accumulation over sorted runs ---
    float4 acc = make_float4(0.f, 0.f, 0.f, 0.f);
    float zacc = 0.f;
    int cur_d = d0;

    int s2, d2;
    float4 kk2, qq2, vv1;
#pragma unroll
    for (int it = 0; it < 8; it++) {
        if (it < 7)
            vv1 = __ldg(reinterpret_cast<const float4*>(&g_V[(long)s1 * D + 4 * g]));
        if (it < 6) {
            s2 = __shfl_sync(0xFFFFFFFFu, sd, half * 8 + it + 2);
            d2 = __shfl_sync(0xFFFFFFFFu, sd, 16 + half * 8 + it + 2);
            kk2 = __ldg(reinterpret_cast<const float4*>(&g_K[(long)s2 * D + 4 * g]));
            qq2 = __ldg(reinterpret_cast<const float4*>(&g_Q[(long)d2 * D + 4 * g]));
        }

        int r = half * 8 + it;
        float4 ef = *reinterpret_cast<const float4*>(
            &sEf[warp][r][(4 * g) ^ ((r & 7) << 3)]);

        float p = (kk0.x * qq0.x) * ef.x;
        p = fmaf(kk0.y * qq0.y, ef.y, p);
        p = fmaf(kk0.z * qq0.z, ef.z, p);
        p = fmaf(kk0.w * qq0.w, ef.w, p);
        p += __shfl_xor_sync(0xFFFFFFFFu, p, 1);

        float sv = fminf(14.142135623730951f, fmaxf(-14.142135623730951f, p));
        float sc = exp2f(sv * 0.51002501915290554f);

        if (d0 != cur_d) {   // uniform across half-warp
            red_add_v4(&out[(long)cur_d * D + 4 * g], acc.x, acc.y, acc.z, acc.w);
            if ((g & 1) == 0) atomicAdd(&g_Z[cur_d * H + (g >> 1)], zacc);
            acc = make_float4(0.f, 0.f, 0.f, 0.f);
            zacc = 0.f;
            cur_d = d0;
        }
        acc.x = fmaf(vv0.x, sc, acc.x);
        acc.y = fmaf(vv0.y, sc, acc.y);
        acc.z = fmaf(vv0.z, sc, acc.z);
        acc.w = fmaf(vv0.w, sc, acc.w);
        zacc += sc;

        kk0 = kk1; qq0 = qq1; vv0 = vv1; s0 = s1; d0 = d1;
        kk1 = kk2; qq1 = qq2; s1 = s2; d1 = d2;
    }

    // final flush
    red_add_v4(&out[(long)cur_d * D + 4 * g], acc.x, acc.y, acc.z, acc.w);
    if ((g & 1) == 0) atomicAdd(&g_Z[cur_d * H + (g >> 1)], zacc);
}

// ---------------------------------------------------------------------------
// K3: out = wV / (Z + 1e-6)
// ---------------------------------------------------------------------------
__global__ void div_kernel(float4* __restrict__ out4) {
    int i = blockIdx.x * blockDim.x + threadIdx.x;
    if (i >= (N_NODES * D) / 4) return;
    int n  = i >> 4;
    int c4 = i & 15;
    int h  = c4 >> 1;
    float r = 1.0f / (g_Z[n * H + h] + 1e-6f);
    float4 v = out4[i];
    v.x *= r; v.y *= r; v.z *= r; v.w *= r;
    out4[i] = v;
}

// ---------------------------------------------------------------------------
extern "C" void kernel_launch(void* const* d_in, const int* in_sizes, int n_in,
                              void* d_out, int out_size)
{
    const float* x   = (const float*)d_in[0];
    const float* ea  = (const float*)d_in[1];
    const float* WQ  = (const float*)d_in[2];
    const float* WK  = (const float*)d_in[3];
    const float* WV  = (const float*)d_in[4];
    const float* WE  = (const float*)d_in[5];
    const int*   ei  = (const int*)d_in[6];
    float* out = (float*)d_out;

    (void)in_sizes; (void)n_in; (void)out_size;

    // counting sort by dst (rebuilt every call; deterministic work)
    zero_cnt_kernel<<<NB, 256>>>();
    hist_kernel<<<(NEDGES + 255) / 256, 256>>>(ei);
    scan1_kernel<<<NB, 256>>>();
    scan2_kernel<<<1, 512>>>();
    scan3_kernel<<<NB, 256>>>();
    scatter_kernel<<<(NEDGES + 255) / 256, 256>>>(ei);

    proj_kernel<<<(N_NODES / 16 + 7) / 8, 256>>>(x, WQ, WK, WV, out);
    fused_edge_kernel<<<(NEDGES / 16 + 7) / 8, 256>>>(ea, WE, out);
    div_kernel<<<(N_NODES * D / 4 + 255) / 256, 256>>>((float4*)out);
}

// round 14
// speedup vs baseline: 1.3426x; 1.2188x over previous
#include <cuda_runtime.h>
#include <cuda_fp16.h>

#define N_NODES 100000
#define NEDGES  1250000
#define D       64
#define H       8
#define NTILES  (N_NODES / 16)   // 6250
// DH = 8, scale = 1/sqrt(8)

// Scratch (static __device__ arrays: allocation-free per harness rules)
__device__ float g_Q[N_NODES * D];
__device__ float g_K[N_NODES * D];
__device__ float g_V[N_NODES * D];
__device__ float g_Z[N_NODES * H];

// ---------------------------------------------------------------------------
// helpers
// ---------------------------------------------------------------------------
__device__ __forceinline__ void red_add_v4(float* p, float x, float y, float z, float w) {
    asm volatile("red.global.add.v4.f32 [%0], {%1, %2, %3, %4};"
                 :: "l"(p), "f"(x), "f"(y), "f"(z), "f"(w) : "memory");
}

// split a float2 into hi/lo packed f16x2 (hi + lo recovers ~22 mantissa bits)
__device__ __forceinline__ void split_f16x2(float2 v, unsigned& h, unsigned& l) {
    __half2 hb = __floats2half2_rn(v.x, v.y);
    float2 hf = __half22float2(hb);
    __half2 lb = __floats2half2_rn(v.x - hf.x, v.y - hf.y);
    h = *reinterpret_cast<unsigned*>(&hb);
    l = *reinterpret_cast<unsigned*>(&lb);
}

__device__ __forceinline__ unsigned pack_f16x2(float a, float b) {
    __half2 hb = __floats2half2_rn(a, b);
    return *reinterpret_cast<unsigned*>(&hb);
}

// D += A(f16) * B(f16), m16n8k16, f32 accumulate
__device__ __forceinline__ void mma_f16(float* c, const unsigned* a,
                                        unsigned b0, unsigned b1) {
    asm volatile(
        "mma.sync.aligned.m16n8k16.row.col.f32.f16.f16.f32 "
        "{%0,%1,%2,%3}, {%4,%5,%6,%7}, {%8,%9}, {%0,%1,%2,%3};"
        : "+f"(c[0]), "+f"(c[1]), "+f"(c[2]), "+f"(c[3])
        : "r"(a[0]), "r"(a[1]), "r"(a[2]), "r"(a[3]), "r"(b0), "r"(b1));
}

// ---------------------------------------------------------------------------
// K1: QKV projections via fp16-split tensor-core mma, 3-pass (hh + hl + lh).
// Grid-stride over 16-node tiles (2 tiles/warp at grid=391, single wave).
// Weight staging is COALESCED: raw W -> SMEM via float4 LDG, fragments built
// from SMEM via LDS. Raw mats ping-pong through not-yet-built sB regions so
// static SMEM stays at 48 KB. Also zeroes out[] rows and g_Z rows.
// ---------------------------------------------------------------------------
__global__ __launch_bounds__(256) void proj_kernel(
    const float* __restrict__ x,
    const float* __restrict__ WQ,
    const float* __restrict__ WK,
    const float* __restrict__ WV,
    float* __restrict__ out)
{
    // [mat][ntile][kstep][lane] = (bh0, bh1, bl0, bl1)
    __shared__ uint4 sB[3][8][4][32];   // 48 KB

    const int tid = threadIdx.x;

    // ---- coalesced staging + fragment build ----
    // raw W lives temporarily in a 16 KB region of sB that has no fragments yet
    {
        float* raw1 = reinterpret_cast<float*>(&sB[1][0][0][0]);
        float* raw2 = reinterpret_cast<float*>(&sB[2][0][0][0]);

        // mat 0: raw WQ -> sB[1] region, build frags -> sB[0]
        for (int i = tid; i < 1024; i += 256)
            reinterpret_cast<float4*>(raw1)[i] = __ldg(&reinterpret_cast<const float4*>(WQ)[i]);
        __syncthreads();
        for (int t = tid; t < 1024; t += 256) {
            int n = t >> 7, k = (t >> 5) & 3, l = t & 31;
            int tig = l & 3, grp = l >> 2;
            int col = n * 8 + grp, r0 = k * 16 + 2 * tig;
            float2 w0 = make_float2(raw1[r0 * D + col],       raw1[(r0 + 1) * D + col]);
            float2 w1 = make_float2(raw1[(r0 + 8) * D + col], raw1[(r0 + 9) * D + col]);
            unsigned h0, l0, h1, l1;
            split_f16x2(w0, h0, l0);
            split_f16x2(w1, h1, l1);
            sB[0][n][k][l] = make_uint4(h0, h1, l0, l1);
        }
        __syncthreads();

        // mat 1: raw WK -> sB[2] region, build frags -> sB[1]
        for (int i = tid; i < 1024; i += 256)
            reinterpret_cast<float4*>(raw2)[i] = __ldg(&reinterpret_cast<const float4*>(WK)[i]);
        __syncthreads();
        for (int t = tid; t < 1024; t += 256) {
            int n = t >> 7, k = (t >> 5) & 3, l = t & 31;
            int tig = l & 3, grp = l >> 2;
            int col = n * 8 + grp, r0 = k * 16 + 2 * tig;
            float2 w0 = make_float2(raw2[r0 * D + col],       raw2[(r0 + 1) * D + col]);
            float2 w1 = make_float2(raw2[(r0 + 8) * D + col], raw2[(r0 + 9) * D + col]);
            unsigned h0, l0, h1, l1;
            split_f16x2(w0, h0, l0);
            split_f16x2(w1, h1, l1);
            sB[1][n][k][l] = make_uint4(h0, h1, l0, l1);
        }
        __syncthreads();

        // mat 2: raw WV -> sB[2] region (overwrites dead raw WK), then
        // in-place build: read raw into registers, sync, write frags.
        for (int i = tid; i < 1024; i += 256)
            reinterpret_cast<float4*>(raw2)[i] = __ldg(&reinterpret_cast<const float4*>(WV)[i]);
        __syncthreads();
        uint4 frag[4];
        int   fidx[4];
        for (int t = tid, j = 0; t < 1024; t += 256, j++) {
            int n = t >> 7, k = (t >> 5) & 3, l = t & 31;
            int tig = l & 3, grp = l >> 2;
            int col = n * 8 + grp, r0 = k * 16 + 2 * tig;
            float2 w0 = make_float2(raw2[r0 * D + col],       raw2[(r0 + 1) * D + col]);
            float2 w1 = make_float2(raw2[(r0 + 8) * D + col], raw2[(r0 + 9) * D + col]);
            unsigned h0, l0, h1, l1;
            split_f16x2(w0, h0, l0);
            split_f16x2(w1, h1, l1);
            frag[j] = make_uint4(h0, h1, l0, l1);
            fidx[j] = t;
        }
        __syncthreads();
#pragma unroll
        for (int j = 0; j < 4; j++) {
            int t = fidx[j];
            int n = t >> 7, k = (t >> 5) & 3, l = t & 31;
            sB[2][n][k][l] = frag[j];
        }
        __syncthreads();
    }

    const int warp = tid >> 5;
    const int lane = tid & 31;
    const int grp = lane >> 2;
    const int tig = lane & 3;

    float* Outs[3] = {g_Q, g_K, g_V};

    for (int tile = blockIdx.x * 8 + warp; tile < NTILES; tile += gridDim.x * 8) {
        const long row0 = (long)tile * 16 + grp;
        const long row1 = row0 + 8;

        // --- A fragments from x (hi/lo fp16 split) ---
        unsigned Ah[4][4], Al[4][4];
#pragma unroll
        for (int k = 0; k < 4; k++) {
            float2 x0 = __ldg(reinterpret_cast<const float2*>(x + row0 * D + k * 16 + 2 * tig));
            float2 x1 = __ldg(reinterpret_cast<const float2*>(x + row1 * D + k * 16 + 2 * tig));
            float2 x2 = __ldg(reinterpret_cast<const float2*>(x + row0 * D + k * 16 + 8 + 2 * tig));
            float2 x3 = __ldg(reinterpret_cast<const float2*>(x + row1 * D + k * 16 + 8 + 2 * tig));
            split_f16x2(x0, Ah[k][0], Al[k][0]);
            split_f16x2(x1, Ah[k][1], Al[k][1]);
            split_f16x2(x2, Ah[k][2], Al[k][2]);
            split_f16x2(x3, Ah[k][3], Al[k][3]);
        }

#pragma unroll
        for (int w = 0; w < 3; w++) {
            float* O = Outs[w];
#pragma unroll
            for (int n = 0; n < 8; n++) {
                uint4 b[4];
#pragma unroll
                for (int k = 0; k < 4; k++) b[k] = sB[w][n][k][lane];

                float c1[4] = {0.f, 0.f, 0.f, 0.f};
                float c2[4] = {0.f, 0.f, 0.f, 0.f};
                float c3[4] = {0.f, 0.f, 0.f, 0.f};
#pragma unroll
                for (int k = 0; k < 4; k++) {
                    mma_f16(c1, Ah[k], b[k].x, b[k].y);   // hh
                    mma_f16(c2, Ah[k], b[k].z, b[k].w);   // h*l
                    mma_f16(c3, Al[k], b[k].x, b[k].y);   // l*h
                }

                int cc = n * 8 + 2 * tig;
                *reinterpret_cast<float2*>(&O[row0 * D + cc]) =
                    make_float2(c1[0] + c2[0] + c3[0], c1[1] + c2[1] + c3[1]);
                *reinterpret_cast<float2*>(&O[row1 * D + cc]) =
                    make_float2(c1[2] + c2[2] + c3[2], c1[3] + c2[3] + c3[3]);
            }
        }

        // --- zero accumulators for these 16 nodes ---
        float4 z4 = make_float4(0.f, 0.f, 0.f, 0.f);
        float4* o4 = reinterpret_cast<float4*>(out) + (long)tile * 256;
#pragma unroll
        for (int i = 0; i < 8; i++) o4[i * 32 + lane] = z4;
        reinterpret_cast<float4*>(g_Z)[(long)tile * 32 + lane] = z4;
    }
}

// ---------------------------------------------------------------------------
// K2: FUSED edge kernel (round-8 verbatim — measured best). Per warp = 16
// edges. Phase A: Ef tile = ea[16x64] @ WE via fp16 2-pass split mma,
// edge-0/1 K/Q/V gathers issued before the mma loop. Phase B: 16 lanes/edge,
// depth-2 (kk/qq) + depth-1 (vv) software pipeline, red.add.v4 scatter.
// NEDGES % 16 == 0 -> every live warp-tile is full.
// ---------------------------------------------------------------------------
__global__ __launch_bounds__(256) void fused_edge_kernel(
    const float* __restrict__ ea,
    const float* __restrict__ WE,
    const int* __restrict__ ei,
    float* __restrict__ out)
{
    __shared__ uint2 sB[8][4][32];     // 8 KB  (WE fp16 B-fragments)
    __shared__ float sEf[8][16][64];   // 32 KB (per-warp 16x64 Ef tiles)

    const int tid = threadIdx.x;

    for (int t = tid; t < 1024; t += 256) {
        int n = t >> 7, k = (t >> 5) & 3, l = t & 31;
        int tig = l & 3, grp = l >> 2;
        int col = n * 8 + grp;
        int r0 = k * 16 + 2 * tig;
        unsigned b0 = pack_f16x2(__ldg(&WE[r0 * D + col]),       __ldg(&WE[(r0 + 1) * D + col]));
        unsigned b1 = pack_f16x2(__ldg(&WE[(r0 + 8) * D + col]), __ldg(&WE[(r0 + 9) * D + col]));
        sB[n][k][l] = make_uint2(b0, b1);
    }
    __syncthreads();

    const int warp = tid >> 5;
    const int lane = tid & 31;
    const int base = (blockIdx.x * 8 + warp) * 16;
    if (base >= NEDGES) return;

    int sd = __ldg(&ei[(lane >> 4) * NEDGES + base + (lane & 15)]);

    const int half = lane >> 4;
    const int g    = lane & 15;

    int s0 = __shfl_sync(0xFFFFFFFFu, sd, half);
    int d0 = __shfl_sync(0xFFFFFFFFu, sd, 16 + half);
    int s1 = __shfl_sync(0xFFFFFFFFu, sd, 2 + half);
    int d1 = __shfl_sync(0xFFFFFFFFu, sd, 18 + half);
    float4 kk0 = __ldg(reinterpret_cast<const float4*>(&g_K[(long)s0 * D + 4 * g]));
    float4 qq0 = __ldg(reinterpret_cast<const float4*>(&g_Q[(long)d0 * D + 4 * g]));
    float4 vv0 = __ldg(reinterpret_cast<const float4*>(&g_V[(long)s0 * D + 4 * g]));
    float4 kk1 = __ldg(reinterpret_cast<const float4*>(&g_K[(long)s1 * D + 4 * g]));
    float4 qq1 = __ldg(reinterpret_cast<const float4*>(&g_Q[(long)d1 * D + 4 * g]));

    const int grp = lane >> 2;
    const int tig = lane & 3;
    const long row0 = base + grp;
    const long row1 = row0 + 8;

    unsigned Ah[4][4], Al[4][4];
#pragma unroll
    for (int k = 0; k < 4; k++) {
        float2 x0 = __ldcs(reinterpret_cast<const float2*>(ea + row0 * D + k * 16 + 2 * tig));
        float2 x1 = __ldcs(reinterpret_cast<const float2*>(ea + row1 * D + k * 16 + 2 * tig));
        float2 x2 = __ldcs(reinterpret_cast<const float2*>(ea + row0 * D + k * 16 + 8 + 2 * tig));
        float2 x3 = __ldcs(reinterpret_cast<const float2*>(ea + row1 * D + k * 16 + 8 + 2 * tig));
        split_f16x2(x0, Ah[k][0], Al[k][0]);
        split_f16x2(x1, Ah[k][1], Al[k][1]);
        split_f16x2(x2, Ah[k][2], Al[k][2]);
        split_f16x2(x3, Ah[k][3], Al[k][3]);
    }

    const int swz = (grp & 7) << 3;
#pragma unroll
    for (int n = 0; n < 8; n++) {
        uint2 b[4];
#pragma unroll
        for (int k = 0; k < 4; k++) b[k] = sB[n][k][lane];

        float c1[4] = {0.f, 0.f, 0.f, 0.f};
        float c2[4] = {0.f, 0.f, 0.f, 0.f};
#pragma unroll
        for (int k = 0; k < 4; k++) {
            mma_f16(c1, Ah[k], b[k].x, b[k].y);
            mma_f16(c2, Al[k], b[k].x, b[k].y);
        }

        int colw = (8 * n + 2 * tig) ^ swz;
        *reinterpret_cast<float2*>(&sEf[warp][grp][colw]) =
            make_float2(c1[0] + c2[0], c1[1] + c2[1]);
        *reinterpret_cast<float2*>(&sEf[warp][grp + 8][colw]) =
            make_float2(c1[2] + c2[2], c1[3] + c2[3]);
    }
    __syncwarp();

    int s2, d2;
    float4 kk2, qq2, vv1;
#pragma unroll
    for (int it = 0; it < 8; it++) {
        if (it < 7)
            vv1 = __ldg(reinterpret_cast<const float4*>(&g_V[(long)s1 * D + 4 * g]));
        if (it < 6) {
            s2 = __shfl_sync(0xFFFFFFFFu, sd, (it + 2) * 2 + half);
            d2 = __shfl_sync(0xFFFFFFFFu, sd, 16 + (it + 2) * 2 + half);
            kk2 = __ldg(reinterpret_cast<const float4*>(&g_K[(long)s2 * D + 4 * g]));
            qq2 = __ldg(reinterpret_cast<const float4*>(&g_Q[(long)d2 * D + 4 * g]));
        }

        int r = it * 2 + half;
        float4 ef = *reinterpret_cast<const float4*>(
            &sEf[warp][r][(4 * g) ^ ((r & 7) << 3)]);

        float p = (kk0.x * qq0.x) * ef.x;
        p = fmaf(kk0.y * qq0.y, ef.y, p);
        p = fmaf(kk0.z * qq0.z, ef.z, p);
        p = fmaf(kk0.w * qq0.w, ef.w, p);
        p += __shfl_xor_sync(0xFFFFFFFFu, p, 1);

        // clamp in p-domain (+-5*sqrt(8)); exp(x/sqrt8)=2^(x*log2e/sqrt8)
        float sv = fminf(14.142135623730951f, fmaxf(-14.142135623730951f, p));
        float sc = exp2f(sv * 0.51002501915290554f);

        red_add_v4(&out[(long)d0 * D + 4 * g],
                   vv0.x * sc, vv0.y * sc, vv0.z * sc, vv0.w * sc);
        if ((g & 1) == 0)
            atomicAdd(&g_Z[d0 * H + (g >> 1)], sc);

        kk0 = kk1; qq0 = qq1; vv0 = vv1; s0 = s1; d0 = d1;
        kk1 = kk2; qq1 = qq2; s1 = s2; d1 = d2;
    }
}

// ---------------------------------------------------------------------------
// K3: out = wV / (Z + 1e-6)   (one float4 per thread)
// ---------------------------------------------------------------------------
__global__ void div_kernel(float4* __restrict__ out4) {
    int i = blockIdx.x * blockDim.x + threadIdx.x;
    if (i >= (N_NODES * D) / 4) return;
    int n  = i >> 4;
    int c4 = i & 15;
    int h  = c4 >> 1;
    float r = 1.0f / (g_Z[n * H + h] + 1e-6f);
    float4 v = out4[i];
    v.x *= r; v.y *= r; v.z *= r; v.w *= r;
    out4[i] = v;
}

// ---------------------------------------------------------------------------
extern "C" void kernel_launch(void* const* d_in, const int* in_sizes, int n_in,
                              void* d_out, int out_size)
{
    const float* x   = (const float*)d_in[0];
    const float* ea  = (const float*)d_in[1];
    const float* WQ  = (const float*)d_in[2];
    const float* WK  = (const float*)d_in[3];
    const float* WV  = (const float*)d_in[4];
    const float* WE  = (const float*)d_in[5];
    const int*   ei  = (const int*)d_in[6];
    float* out = (float*)d_out;

    (void)in_sizes; (void)n_in; (void)out_size;

    proj_kernel<<<391, 256>>>(x, WQ, WK, WV, out);
    fused_edge_kernel<<<(NEDGES / 16 + 7) / 8, 256>>>(ea, WE, ei, out);
    div_kernel<<<(N_NODES * D / 4 + 255) / 256, 256>>>((float4*)out);
}